// round 1
// baseline (speedup 1.0000x reference)
#include <cuda_runtime.h>

// JPEG encode: (512,3,128,128) fp32 -> DCT -> quant -> zigzag
// out = [flatten (256,512,192) | no_quan_flatten (256,512,192)] fp32
//
// One thread per 8x8 block. Thread t = (n*512 + b)*3 + c so that the
// flatten output offset is exactly t*64 -> each 128-thread CTA owns a
// contiguous 32KB output range per tensor. DCT results are staged in
// shared memory (scattered into zigzag order, stride-68 padding), then
// written with fully-coalesced float4 stores.

#define BT 128
#define STRIDE 68   // 68*4B = 272B row pitch: 16B-aligned, conflict-friendly

__constant__ int c_zz[64] = {
     0,  1,  8, 16,  9,  2,  3, 10,
    17, 24, 32, 25, 18, 11,  4,  5,
    12, 19, 26, 33, 40, 48, 41, 34,
    27, 20, 13,  6,  7, 14, 21, 28,
    35, 42, 49, 56, 57, 50, 43, 36,
    29, 22, 15, 23, 30, 37, 44, 51,
    58, 59, 52, 45, 38, 31, 39, 46,
    53, 60, 61, 54, 47, 55, 62, 63};

__global__ __launch_bounds__(BT)
void jpeg_encode_kernel(const float* __restrict__ img,
                        const float* __restrict__ Dm,
                        const float* __restrict__ Qm,
                        float* __restrict__ out_q,
                        float* __restrict__ out_nq)
{
    __shared__ float Ds[64];          // DCT matrix
    __shared__ float Qz[64];          // Q in zigzag order: Qz[pos] = Q[zz[pos]]
    __shared__ int   invz[64];        // invz[flat] = zigzag position
    __shared__ float stage[BT * STRIDE];

    const int tid = threadIdx.x;
    if (tid < 64) {
        Ds[tid] = Dm[tid];
        int f   = c_zz[tid];
        invz[f] = tid;
        Qz[tid] = Qm[f];
    }
    __syncthreads();

    // Global block id t = n*1536 + b*3 + c  (B=512, C=3, N=256)
    const long long t = (long long)blockIdx.x * BT + tid;
    const int c  = (int)(t % 3);
    const int bb = (int)((t / 3) % 512);
    const int n  = (int)(t / 1536);
    const int nh = n >> 4;
    const int nw = n & 15;

    // img layout (B, C, 128, 128): plane stride 16384 floats, row stride 128
    const float* src = img + (((size_t)(bb * 3 + c)) << 14)
                           + (size_t)nh * 1024 + (size_t)nw * 8;

    // ---- Stage 1: T = (X - 128) @ D^T  ;  T[r][j] = sum_k x[r][k] * D[j][k]
    float T[64];
#pragma unroll
    for (int r = 0; r < 8; ++r) {
        float4 a = *(const float4*)(src + r * 128);
        float4 b4 = *(const float4*)(src + r * 128 + 4);
        float x[8] = { a.x - 128.f,  a.y - 128.f,  a.z - 128.f,  a.w - 128.f,
                       b4.x - 128.f, b4.y - 128.f, b4.z - 128.f, b4.w - 128.f };
#pragma unroll
        for (int j = 0; j < 8; ++j) {
            float s = 0.f;
#pragma unroll
            for (int k = 0; k < 8; ++k)
                s = fmaf(x[k], Ds[j * 8 + k], s);
            T[r * 8 + j] = s;
        }
    }

    // ---- Stage 2: Y = D @ T ; scatter Y into zigzag order in smem
    float* st = stage + tid * STRIDE;
#pragma unroll
    for (int i = 0; i < 8; ++i) {
#pragma unroll
        for (int j = 0; j < 8; ++j) {
            float y = 0.f;
#pragma unroll
            for (int r = 0; r < 8; ++r)
                y = fmaf(Ds[i * 8 + r], T[r * 8 + j], y);
            st[invz[i * 8 + j]] = y;
        }
    }
    __syncthreads();

    // ---- Cooperative coalesced writes: CTA owns [base, base + 8192) floats
    const size_t base = (size_t)blockIdx.x * (BT * 64);
#pragma unroll
    for (int it = 0; it < 16; ++it) {
        const int j   = it * 512 + tid * 4;   // 0..8191, 16B aligned
        const int lt  = j >> 6;               // which local block
        const int pos = j & 63;               // zigzag position (multiple of 4)
        float4 v = *(const float4*)(stage + lt * STRIDE + pos);
        float4 q;
        q.x = rintf(v.x / Qz[pos + 0]);
        q.y = rintf(v.y / Qz[pos + 1]);
        q.z = rintf(v.z / Qz[pos + 2]);
        q.w = rintf(v.w / Qz[pos + 3]);
        *(float4*)(out_nq + base + j) = v;
        *(float4*)(out_q  + base + j) = q;
    }
}

extern "C" void kernel_launch(void* const* d_in, const int* in_sizes, int n_in,
                              void* d_out, int out_size)
{
    const float* img = (const float*)d_in[0];   // (512,3,128,128) fp32
    const float* Dm  = (const float*)d_in[1];   // (8,8) fp32
    const float* Qm  = (const float*)d_in[2];   // (8,8) fp32
    float* out = (float*)d_out;

    const size_t half = (size_t)out_size / 2;   // flatten | no_quan_flatten
    // 512*3*256 = 393216 blocks, 128 per CTA -> 3072 CTAs
    jpeg_encode_kernel<<<3072, BT>>>(img, Dm, Qm, out, out + half);
}

// round 2
// speedup vs baseline: 1.6401x; 1.6401x over previous
#include <cuda_runtime.h>

// JPEG encode: (512,3,128,128) fp32 -> -128 -> 8x8 DCT -> quant -> zigzag
// out = [flatten (256,512,192) | no_quan_flatten (256,512,192)] fp32
//
// One thread per 8x8 block, t = (n*512 + b)*3 + c  ==> flatten offset = t*64,
// so each 128-thread CTA owns a contiguous 32KB range per output tensor.
//
// R2: zigzag done via compile-time register renaming (Yz[INVZ(i,j)]),
//     staging uses 16x STS.128 (conflict-free) instead of 64 scattered STS.32,
//     DCT matrix lives in __constant__ so every FMA uses a c[][] operand.

#define BT 128
#define STRIDE 68   // floats; 272B pitch -> conflict-free for 16B ld/st

__constant__ float cD[64];     // DCT matrix (copied from d_in[1] at launch)

__constant__ int c_zz[64] = {  // zigzag: out position p reads flat index zz[p]
     0,  1,  8, 16,  9,  2,  3, 10,
    17, 24, 32, 25, 18, 11,  4,  5,
    12, 19, 26, 33, 40, 48, 41, 34,
    27, 20, 13,  6,  7, 14, 21, 28,
    35, 42, 49, 56, 57, 50, 43, 36,
    29, 22, 15, 23, 30, 37, 44, 51,
    58, 59, 52, 45, 38, 31, 39, 46,
    53, 60, 61, 54, 47, 55, 62, 63};

// inverse zigzag: flat index f lands at zigzag position INVZ[f] (compile-time)
static __device__ constexpr int INVZ[64] = {
     0,  1,  5,  6, 14, 15, 27, 28,
     2,  4,  7, 13, 16, 26, 29, 42,
     3,  8, 12, 17, 25, 30, 41, 43,
     9, 11, 18, 24, 31, 40, 44, 53,
    10, 19, 23, 32, 39, 45, 52, 54,
    20, 22, 33, 38, 46, 51, 55, 60,
    21, 34, 37, 47, 50, 56, 59, 61,
    35, 36, 48, 49, 57, 58, 62, 63};

__global__ __launch_bounds__(BT)
void jpeg_encode_kernel(const float* __restrict__ img,
                        const float* __restrict__ Qm,
                        float* __restrict__ out_q,
                        float* __restrict__ out_nq)
{
    __shared__ float Qz[64];               // Q in zigzag order
    __shared__ float stage[BT * STRIDE];

    const int tid = threadIdx.x;
    if (tid < 64) Qz[tid] = Qm[c_zz[tid]];

    // global block id t = n*1536 + b*3 + c   (B=512, C=3, N=256)
    const long long t = (long long)blockIdx.x * BT + tid;
    const int c  = (int)(t % 3);
    const int bb = (int)((t / 3) % 512);
    const int n  = (int)(t / 1536);

    // img (B,C,128,128): plane stride 16384 floats, row stride 128
    const float* src = img + (((size_t)(bb * 3 + c)) << 14)
                           + (size_t)(n >> 4) * 1024 + (size_t)(n & 15) * 8;

    // ---- fused DCT, outer product over input rows, zigzag-renamed accumulator
    // Y[i][j] = sum_r D[i][r] * T[r][j],  T[r][j] = sum_k (x[r][k]-128) D[j][k]
    float Yz[64];
#pragma unroll
    for (int p = 0; p < 64; ++p) Yz[p] = 0.f;

#pragma unroll
    for (int r = 0; r < 8; ++r) {
        float4 a  = *(const float4*)(src + r * 128);
        float4 b4 = *(const float4*)(src + r * 128 + 4);
        float x[8] = { a.x - 128.f,  a.y - 128.f,  a.z - 128.f,  a.w - 128.f,
                       b4.x - 128.f, b4.y - 128.f, b4.z - 128.f, b4.w - 128.f };
        float Tr[8];
#pragma unroll
        for (int j = 0; j < 8; ++j) {
            float s = 0.f;
#pragma unroll
            for (int k = 0; k < 8; ++k)
                s = fmaf(x[k], cD[j * 8 + k], s);
            Tr[j] = s;
        }
#pragma unroll
        for (int i = 0; i < 8; ++i)
#pragma unroll
            for (int j = 0; j < 8; ++j)
                Yz[INVZ[i * 8 + j]] = fmaf(cD[i * 8 + r], Tr[j], Yz[INVZ[i * 8 + j]]);
    }

    // ---- stage (already zigzag-ordered): 16 conflict-free STS.128
    float* st = stage + tid * STRIDE;
#pragma unroll
    for (int k = 0; k < 16; ++k) {
        float4 v = make_float4(Yz[4 * k], Yz[4 * k + 1], Yz[4 * k + 2], Yz[4 * k + 3]);
        *(float4*)(st + 4 * k) = v;
    }
    __syncthreads();

    // ---- cooperative coalesced writes: CTA owns [base, base + 8192) floats
    const size_t base = (size_t)blockIdx.x * (BT * 64);
#pragma unroll
    for (int it = 0; it < 16; ++it) {
        const int j   = it * 512 + tid * 4;   // 0..8191, 16B aligned
        const int lt  = j >> 6;               // local block
        const int pos = j & 63;               // zigzag position (mult of 4)
        float4 v  = *(const float4*)(stage + lt * STRIDE + pos);
        float4 qv = *(const float4*)(Qz + pos);
        float4 q;
        q.x = rintf(v.x / qv.x);
        q.y = rintf(v.y / qv.y);
        q.z = rintf(v.z / qv.z);
        q.w = rintf(v.w / qv.w);
        *(float4*)(out_nq + base + j) = v;
        *(float4*)(out_q  + base + j) = q;
    }
}

extern "C" void kernel_launch(void* const* d_in, const int* in_sizes, int n_in,
                              void* d_out, int out_size)
{
    const float* img = (const float*)d_in[0];   // (512,3,128,128) fp32
    const float* Dm  = (const float*)d_in[1];   // (8,8) fp32
    const float* Qm  = (const float*)d_in[2];   // (8,8) fp32
    float* out = (float*)d_out;

    // D -> constant memory (graph-capturable D2D memcpy node)
    cudaMemcpyToSymbolAsync(cD, Dm, 64 * sizeof(float), 0,
                            cudaMemcpyDeviceToDevice, 0);

    const size_t half = (size_t)out_size / 2;   // flatten | no_quan_flatten
    jpeg_encode_kernel<<<3072, BT>>>(img, Qm, out, out + half);
}

// round 3
// speedup vs baseline: 2.2575x; 1.3765x over previous
#include <cuda_runtime.h>

// JPEG encode: (512,3,128,128) fp32 -> -128 -> 8x8 DCT -> quant -> zigzag
// out = [flatten (256,512,192) | no_quan_flatten (256,512,192)] fp32
//
// R3: coalesced-read work mapping (CTA = 8 planes x 16 width-blocks, so each
//     half-warp sweeps a contiguous 512B image row), butterfly DCT with the
//     DCT-II matrix baked in as FFMA immediates, -128 bias folded into the DC
//     coefficient, division replaced by a hoisted reciprocal, smem stage keeps
//     stores perfectly coalesced.

#define BT 128
#define STRIDE 68   // floats; 272B slot pitch -> conflict-free 16B ld/st

// 0.5*cos(k*pi/16), double-precision literals rounded to float
#define C1f 0.49039264020161522f
#define C2f 0.46193976625564338f
#define C3f 0.41573480615127262f
#define C4f 0.35355339059327376f
#define C5f 0.27778511650980111f
#define C6f 0.19134171618254489f
#define C7f 0.09754516100806413f

// D[j][k] for k=0..3 (k=4..7 follow by even/odd symmetry)
__device__ constexpr float DC[8][4] = {
    { C4f,  C4f,  C4f,  C4f},
    { C1f,  C3f,  C5f,  C7f},
    { C2f,  C6f, -C6f, -C2f},
    { C3f, -C7f, -C1f, -C5f},
    { C4f, -C4f, -C4f,  C4f},
    { C5f, -C1f,  C7f,  C3f},
    { C6f, -C2f,  C2f, -C6f},
    { C7f, -C5f,  C3f, -C1f}};

__constant__ int c_zz[64] = {  // zigzag position p reads flat index zz[p]
     0,  1,  8, 16,  9,  2,  3, 10,
    17, 24, 32, 25, 18, 11,  4,  5,
    12, 19, 26, 33, 40, 48, 41, 34,
    27, 20, 13,  6,  7, 14, 21, 28,
    35, 42, 49, 56, 57, 50, 43, 36,
    29, 22, 15, 23, 30, 37, 44, 51,
    58, 59, 52, 45, 38, 31, 39, 46,
    53, 60, 61, 54, 47, 55, 62, 63};

// inverse zigzag: flat (i*8+j) lands at zigzag position INVZ[i*8+j]
__device__ constexpr int INVZ[64] = {
     0,  1,  5,  6, 14, 15, 27, 28,
     2,  4,  7, 13, 16, 26, 29, 42,
     3,  8, 12, 17, 25, 30, 41, 43,
     9, 11, 18, 24, 31, 40, 44, 53,
    10, 19, 23, 32, 39, 45, 52, 54,
    20, 22, 33, 38, 46, 51, 55, 60,
    21, 34, 37, 47, 50, 56, 59, 61,
    35, 36, 48, 49, 57, 58, 62, 63};

// Row DCT of one image row via even/odd butterfly: T[j], j=0..7
__device__ __forceinline__ void row_dct(const float* __restrict__ rsrc, float T[8])
{
    float4 a = *(const float4*)rsrc;
    float4 b = *(const float4*)(rsrc + 4);
    float e0 = a.x + b.w, e1 = a.y + b.z, e2 = a.z + b.y, e3 = a.w + b.x;
    float o0 = a.x - b.w, o1 = a.y - b.z, o2 = a.z - b.y, o3 = a.w - b.x;
#pragma unroll
    for (int j = 0; j < 8; j += 2) {
        T[j]     = fmaf(e3, DC[j][3],   fmaf(e2, DC[j][2],   fmaf(e1, DC[j][1],   e0 * DC[j][0])));
        T[j + 1] = fmaf(o3, DC[j+1][3], fmaf(o2, DC[j+1][2], fmaf(o1, DC[j+1][1], o0 * DC[j+1][0])));
    }
}

__global__ __launch_bounds__(BT, 5)
void jpeg_encode_kernel(const float* __restrict__ img,
                        const float* __restrict__ Qm,
                        float* __restrict__ out_q,
                        float* __restrict__ out_nq)
{
    __shared__ float Qinv[64];             // 1/Q in zigzag order
    __shared__ float stage[BT * STRIDE];

    const int tid = threadIdx.x;
    if (tid < 64) Qinv[tid] = 1.0f / Qm[c_zz[tid]];

    // CTA = (nh, group of 8 planes); thread = (plane-in-group, nw)
    const int bid = blockIdx.x;            // 0..3071
    const int nh  = bid / 192;             // 0..15  (block-row)
    const int bcg = bid % 192;             // plane group (8 planes each)
    const int bc  = bcg * 8 + (tid >> 4);  // plane = b*3+c
    const int nw  = tid & 15;              // block-col

    // img (B,C,128,128): plane stride 16384 floats, row stride 128
    const float* src = img + ((size_t)bc << 14) + (size_t)nh * 1024 + (size_t)nw * 8;

    // ---- 2D DCT, butterfly both passes, zigzag-renamed accumulators
    float Yz[64];
#pragma unroll
    for (int p = 0; p < 64; ++p) Yz[p] = 0.f;

#pragma unroll
    for (int rp = 0; rp < 4; ++rp) {       // row pair (rp, 7-rp)
        float Ta[8], Tb[8];
        row_dct(src + rp * 128,       Ta);
        row_dct(src + (7 - rp) * 128, Tb);
#pragma unroll
        for (int j = 0; j < 8; ++j) {
            float s = Ta[j] + Tb[j];       // feeds even output rows
            float d = Ta[j] - Tb[j];       // feeds odd output rows
#pragma unroll
            for (int h = 0; h < 4; ++h) {
                Yz[INVZ[(2*h)    *8 + j]] = fmaf(s, DC[2*h][rp],     Yz[INVZ[(2*h)    *8 + j]]);
                Yz[INVZ[(2*h + 1)*8 + j]] = fmaf(d, DC[2*h + 1][rp], Yz[INVZ[(2*h + 1)*8 + j]]);
            }
        }
    }
    // fold the (x - 128) bias: only the DC coefficient is affected
    Yz[0] -= 1024.0f;                      // INVZ[0] == 0

    // ---- stage (zigzag-ordered): 16 conflict-free STS.128
    float* st = stage + tid * STRIDE;
#pragma unroll
    for (int k = 0; k < 16; ++k)
        *(float4*)(st + 4 * k) =
            make_float4(Yz[4*k], Yz[4*k + 1], Yz[4*k + 2], Yz[4*k + 3]);
    __syncthreads();

    // ---- coalesced writes: 16 regions of 2KB (one per nw), both tensors
    // region it starts at output block (nh*16+it)*1536 + bcg*8
    const size_t obase = (size_t)nh * (16 * 98304) + (size_t)bcg * 512 + tid * 4;
    const int slotbase = (tid >> 4) * 16;      // stage slot = bcl*16 + it
    const int pos      = (tid & 15) * 4;       // zigzag pos within block
    const float4 qv    = *(const float4*)(Qinv + pos);
#pragma unroll
    for (int it = 0; it < 16; ++it) {
        float4 v = *(const float4*)(stage + (slotbase + it) * STRIDE + pos);
        float4 q = make_float4(rintf(v.x * qv.x), rintf(v.y * qv.y),
                               rintf(v.z * qv.z), rintf(v.w * qv.w));
        const size_t o = obase + (size_t)it * 98304;
        *(float4*)(out_nq + o) = v;
        *(float4*)(out_q  + o) = q;
    }
}

extern "C" void kernel_launch(void* const* d_in, const int* in_sizes, int n_in,
                              void* d_out, int out_size)
{
    const float* img = (const float*)d_in[0];   // (512,3,128,128) fp32
    const float* Qm  = (const float*)d_in[2];   // (8,8) fp32
    float* out = (float*)d_out;

    const size_t half = (size_t)out_size / 2;   // flatten | no_quan_flatten
    jpeg_encode_kernel<<<3072, BT>>>(img, Qm, out, out + half);
}